// round 8
// baseline (speedup 1.0000x reference)
#include <cuda_runtime.h>
#include <cuda.h>
#include <cuda_fp16.h>
#include <cstdint>

// ---------------------------------------------------------------------------
// Problem dims (fixed by the dataset)
// ---------------------------------------------------------------------------
#define BATCH 8
#define TDIM 256
#define UDIM 64
#define ENC_DIM 512
#define PRED_DIM 640
#define JOINT_DIM 512
#define VOCAB 1024
#define MROWS (BATCH * TDIM * UDIM) // 131072

// ---------------------------------------------------------------------------
// Scratch (static __device__ arrays -- allocation-free per harness rules)
// ---------------------------------------------------------------------------
__device__ __align__(128) __half g_encH[BATCH * TDIM * ENC_DIM];
__device__ __align__(128) __half g_predH[BATCH * UDIM * PRED_DIM];
__device__ __align__(128) __half g_WencH[ENC_DIM * JOINT_DIM];
__device__ __align__(128) __half g_WpredH[PRED_DIM * JOINT_DIM];
__device__ __align__(128) __half g_WjH[JOINT_DIM * VOCAB];        // [K,V] (fallback)
__device__ __align__(128) __half g_WjT[VOCAB * JOINT_DIM];        // [V,K] (TMA path)
__device__ __align__(128) float  g_encP[BATCH * TDIM * JOINT_DIM];
__device__ __align__(128) float  g_predP[BATCH * UDIM * JOINT_DIM];
__device__ __align__(128) __half g_A[(size_t)MROWS * JOINT_DIM];  // 134 MB

// ---------------------------------------------------------------------------
// Helpers
// ---------------------------------------------------------------------------
__device__ __forceinline__ float tanh_ap(float x) {
    float y;
    asm("tanh.approx.f32 %0, %1;" : "=f"(y) : "f"(x));
    return y;
}
__device__ __forceinline__ uint32_t s2u(const void* p) {
    return (uint32_t)__cvta_generic_to_shared(p);
}
__device__ __forceinline__ void cpa16(uint32_t sa, const void* g) {
    asm volatile("cp.async.cg.shared.global [%0], [%1], 16;\n" :: "r"(sa), "l"(g));
}
__device__ __forceinline__ void mbar_init(uint32_t a, uint32_t cnt) {
    asm volatile("mbarrier.init.shared.b64 [%0], %1;" :: "r"(a), "r"(cnt) : "memory");
}
__device__ __forceinline__ void mbar_expect_tx(uint32_t a, uint32_t bytes) {
    asm volatile("mbarrier.arrive.expect_tx.shared.b64 _, [%0], %1;"
                 :: "r"(a), "r"(bytes) : "memory");
}
__device__ __forceinline__ void mbar_wait(uint32_t a, uint32_t parity) {
    asm volatile(
        "{\n\t.reg .pred P1;\n\t"
        "LAB_WAIT_%=:\n\t"
        "mbarrier.try_wait.parity.acquire.cta.shared::cta.b64 P1, [%0], %1, 0x989680;\n\t"
        "@P1 bra.uni LAB_DONE_%=;\n\t"
        "bra.uni LAB_WAIT_%=;\n\t"
        "LAB_DONE_%=:\n\t}"
        :: "r"(a), "r"(parity) : "memory");
}
__device__ __forceinline__ void tma2d(uint32_t saddr, const CUtensorMap* map,
                                      int x, int y, uint32_t mbar) {
    asm volatile(
        "cp.async.bulk.tensor.2d.shared::cta.global.tile.mbarrier::complete_tx::bytes "
        "[%0], [%1, {%2, %3}], [%4];"
        :: "r"(saddr), "l"(map), "r"(x), "r"(y), "r"(mbar) : "memory");
}

// ---------------------------------------------------------------------------
// Kernel 1: fp32 -> fp16 conversion + W_joint transpose (region-dispatched)
// ---------------------------------------------------------------------------
__global__ void convert_kernel(const float* __restrict__ enc,
                               const float* __restrict__ pred,
                               const float* __restrict__ we,
                               const float* __restrict__ wp,
                               const float* __restrict__ wj) {
    __shared__ float t[64][65];
    int blk = blockIdx.x;
    int tid = threadIdx.x;
    if (blk >= 2432) {
        int tile = blk - 2432;
        int v0 = (tile & 15) * 64;
        int j0 = (tile >> 4) * 64;
#pragma unroll
        for (int i = 0; i < 16; i++) {
            int e = i * 256 + tid;
            int j = e >> 6, v = e & 63;
            t[j][v] = wj[(size_t)(j0 + j) * VOCAB + v0 + v];
        }
        __syncthreads();
#pragma unroll
        for (int i = 0; i < 16; i++) {
            int e = i * 256 + tid;
            int v = e >> 6, j = e & 63;
            g_WjT[(size_t)(v0 + v) * JOINT_DIM + j0 + j] = __float2half(t[j][v]);
        }
        return;
    }
    const float* src;
    __half* dst;
    int lb;
    if (blk < 1024)      { src = enc;  dst = g_encH;   lb = blk; }
    else if (blk < 1344) { src = pred; dst = g_predH;  lb = blk - 1024; }
    else if (blk < 1600) { src = we;   dst = g_WencH;  lb = blk - 1344; }
    else if (blk < 1920) { src = wp;   dst = g_WpredH; lb = blk - 1600; }
    else                 { src = wj;   dst = g_WjH;    lb = blk - 1920; }
    int idx = lb * 1024 + tid * 4;
    float4 v = *reinterpret_cast<const float4*>(src + idx);
    __half2 h0 = __floats2half2_rn(v.x, v.y);
    __half2 h1 = __floats2half2_rn(v.z, v.w);
    uint2 o;
    o.x = *reinterpret_cast<uint32_t*>(&h0);
    o.y = *reinterpret_cast<uint32_t*>(&h1);
    *reinterpret_cast<uint2*>(dst + idx) = o;
}

// ---------------------------------------------------------------------------
// Shared HGEMM body (cp.async path) for projections + legacy fallback.
// ---------------------------------------------------------------------------
#define KSTEP 32
#define STAGES 3
#define A_LD 40
#define B_LD 136
#define A_STGL (128 * A_LD)
#define B_STGL (KSTEP * B_LD)
#define SMEM_BYTES_L ((STAGES * A_STGL + STAGES * B_STGL) * 2)

__device__ __forceinline__ void load_tile(const __half* __restrict__ A,
                                          const __half* __restrict__ Bm,
                                          int K, int N, int m0, int n0, int kt,
                                          __half* aS, __half* bS, int tid) {
    int k0 = kt * KSTEP;
#pragma unroll
    for (int i = 0; i < 2; i++) {
        int idx = tid + i * 256;
        int ar = idx >> 2, ac = (idx & 3) * 8;
        cpa16(s2u(aS + ar * A_LD + ac), A + (size_t)(m0 + ar) * K + k0 + ac);
        int br = idx >> 4, bc = (idx & 15) * 8;
        cpa16(s2u(bS + br * B_LD + bc), Bm + (size_t)(k0 + br) * N + n0 + bc);
    }
}

__device__ __forceinline__ void hgemm_body(const __half* __restrict__ A,
                                           const __half* __restrict__ Bm,
                                           const float* __restrict__ bias,
                                           float* __restrict__ C,
                                           int K, int N, int m0, int n0,
                                           __half* smemBuf) {
    __half* aS = smemBuf;
    __half* bS = smemBuf + STAGES * A_STGL;
    const int tid = threadIdx.x;
    const int lane = tid & 31;
    const int warp = tid >> 5;
    const int wm = warp >> 2;
    const int wn = warp & 3;
    const int kTiles = K / KSTEP;

#pragma unroll
    for (int p = 0; p < STAGES - 1; p++) {
        load_tile(A, Bm, K, N, m0, n0, p, aS + p * A_STGL, bS + p * B_STGL, tid);
        asm volatile("cp.async.commit_group;\n");
    }

    float c[4][4][4];
#pragma unroll
    for (int m = 0; m < 4; m++)
#pragma unroll
        for (int n = 0; n < 4; n++)
#pragma unroll
            for (int r = 0; r < 4; r++) c[m][n][r] = 0.f;

    for (int kt = 0; kt < kTiles; ++kt) {
        asm volatile("cp.async.wait_group %0;\n" :: "n"(STAGES - 2));
        __syncthreads();

        int nx = kt + STAGES - 1;
        if (nx < kTiles)
            load_tile(A, Bm, K, N, m0, n0, nx,
                      aS + (nx % STAGES) * A_STGL, bS + (nx % STAGES) * B_STGL, tid);
        asm volatile("cp.async.commit_group;\n");

        const __half* a = aS + (kt % STAGES) * A_STGL;
        const __half* b = bS + (kt % STAGES) * B_STGL;

#pragma unroll
        for (int kk = 0; kk < 2; ++kk) {
            uint32_t af[4][4];
            uint32_t bf[2][4];
#pragma unroll
            for (int m = 0; m < 4; m++) {
                const __half* p = a + (wm * 64 + m * 16 + (lane & 15)) * A_LD
                                    + kk * 16 + (lane >> 4) * 8;
                uint32_t sa = s2u(p);
                asm volatile("ldmatrix.sync.aligned.m8n8.x4.shared.b16 {%0,%1,%2,%3}, [%4];\n"
                             : "=r"(af[m][0]), "=r"(af[m][1]), "=r"(af[m][2]), "=r"(af[m][3])
                             : "r"(sa));
            }
#pragma unroll
            for (int g = 0; g < 2; g++) {
                const __half* p = b + (kk * 16 + (lane & 15)) * B_LD
                                    + wn * 32 + g * 16 + (lane >> 4) * 8;
                uint32_t sa = s2u(p);
                asm volatile("ldmatrix.sync.aligned.m8n8.x4.trans.shared.b16 {%0,%1,%2,%3}, [%4];\n"
                             : "=r"(bf[g][0]), "=r"(bf[g][1]), "=r"(bf[g][2]), "=r"(bf[g][3])
                             : "r"(sa));
            }
#pragma unroll
            for (int m = 0; m < 4; m++) {
#pragma unroll
                for (int n = 0; n < 4; n++) {
                    uint32_t b0 = bf[n >> 1][(n & 1) * 2];
                    uint32_t b1 = bf[n >> 1][(n & 1) * 2 + 1];
                    asm volatile(
                        "mma.sync.aligned.m16n8k16.row.col.f32.f16.f16.f32 "
                        "{%0,%1,%2,%3}, {%4,%5,%6,%7}, {%8,%9}, {%0,%1,%2,%3};\n"
                        : "+f"(c[m][n][0]), "+f"(c[m][n][1]), "+f"(c[m][n][2]), "+f"(c[m][n][3])
                        : "r"(af[m][0]), "r"(af[m][1]), "r"(af[m][2]), "r"(af[m][3]),
                          "r"(b0), "r"(b1));
                }
            }
        }
    }

    const int mb = m0 + wm * 64;
    const int nb = n0 + wn * 32;
    float2 bb[4];
#pragma unroll
    for (int n = 0; n < 4; n++) {
        int col = nb + n * 8 + (lane & 3) * 2;
        bb[n].x = bias[col];
        bb[n].y = bias[col + 1];
    }
#pragma unroll
    for (int m = 0; m < 4; m++) {
        int row = mb + m * 16 + (lane >> 2);
#pragma unroll
        for (int n = 0; n < 4; n++) {
            int col = nb + n * 8 + (lane & 3) * 2;
            float2 v0 = make_float2(c[m][n][0] + bb[n].x, c[m][n][1] + bb[n].y);
            float2 v1 = make_float2(c[m][n][2] + bb[n].x, c[m][n][3] + bb[n].y);
            __stcs(reinterpret_cast<float2*>(C + (size_t)row * N + col), v0);
            __stcs(reinterpret_cast<float2*>(C + (size_t)(row + 8) * N + col), v1);
        }
    }
}

// Kernel 2: both projections fused into one launch (grid y: 16 enc + 4 pred)
__global__ void __launch_bounds__(256, 2)
proj_kernel(const float* __restrict__ b_enc, const float* __restrict__ b_pred) {
    extern __shared__ __half smemBuf[];
    int y = blockIdx.y;
    if (y < 16)
        hgemm_body(g_encH, g_WencH, b_enc, g_encP, ENC_DIM, JOINT_DIM,
                   y * 128, blockIdx.x * 128, smemBuf);
    else
        hgemm_body(g_predH, g_WpredH, b_pred, g_predP, PRED_DIM, JOINT_DIM,
                   (y - 16) * 128, blockIdx.x * 128, smemBuf);
}

// Fallback big GEMM (cp.async path) -- only used if TMA setup fails
__global__ void __launch_bounds__(256, 2)
legacy_gemm(const float* __restrict__ bias, float* __restrict__ C) {
    extern __shared__ __half smemBuf[];
    hgemm_body(g_A, g_WjH, bias, C, JOINT_DIM, VOCAB,
               blockIdx.y * 128, blockIdx.x * 128, smemBuf);
}

// ---------------------------------------------------------------------------
// Kernel 3: joint = tanh(enc_p[b,t,:] + pred_p[b,u,:]) -> fp16 A matrix.
// Register-resident enc slice: each thread owns a fixed 8-wide j slice
// (loaded once from gmem into registers), walks 16 u-rows. No smem, no
// syncthreads; per-iter LSU = 2x LDG.128 + 1x STG.128 (warp-coalesced).
// ---------------------------------------------------------------------------
__global__ void __launch_bounds__(256) joint_tanh_kernel() {
    const int bt = blockIdx.x;          // 0..2047
    const int tid = threadIdx.x;
    const int b = bt >> 8;
    const int j8 = (tid & 63) * 8;      // fixed 8-col slice
    const int ug = tid >> 6;            // 0..3

    const float4* encRow = reinterpret_cast<const float4*>(
        g_encP + (size_t)bt * JOINT_DIM + j8);
    const float4 e0 = encRow[0];
    const float4 e1 = encRow[1];

    const float* predBase = g_predP + (size_t)(b * UDIM) * JOINT_DIM + j8;
    __half* outBase = g_A + (size_t)bt * UDIM * JOINT_DIM + j8;

#pragma unroll 4
    for (int i = 0; i < 16; i++) {
        int u = i * 4 + ug;             // covers 0..63 across (i, ug)
        const float4* pp = reinterpret_cast<const float4*>(
            predBase + (size_t)u * JOINT_DIM);
        float4 p0 = pp[0], p1 = pp[1];
        __half2 h0 = __floats2half2_rn(tanh_ap(e0.x + p0.x), tanh_ap(e0.y + p0.y));
        __half2 h1 = __floats2half2_rn(tanh_ap(e0.z + p0.z), tanh_ap(e0.w + p0.w));
        __half2 h2 = __floats2half2_rn(tanh_ap(e1.x + p1.x), tanh_ap(e1.y + p1.y));
        __half2 h3 = __floats2half2_rn(tanh_ap(e1.z + p1.z), tanh_ap(e1.w + p1.w));
        uint4 o;
        o.x = *reinterpret_cast<uint32_t*>(&h0);
        o.y = *reinterpret_cast<uint32_t*>(&h1);
        o.z = *reinterpret_cast<uint32_t*>(&h2);
        o.w = *reinterpret_cast<uint32_t*>(&h3);
        *reinterpret_cast<uint4*>(outBase + (size_t)u * JOINT_DIM) = o;
    }
}

// ---------------------------------------------------------------------------
// Kernel 4: TMA big GEMM (round-5 proven mainloop).
// CTA 128x128, KSTEP 64, 3-stage TMA+mbarrier pipeline, SW128 swizzle,
// warp 64x32 mma.sync, 2 CTAs/SM.
// ---------------------------------------------------------------------------
#define TKSTEP 64
#define TSTAGES 3
#define T_ASTG 16384                      // 128 rows x 128B
#define T_STG  32768                      // A + B per stage
#define TSMEM  (1024 + TSTAGES * T_STG)   // 99328 B

__global__ void __launch_bounds__(256, 2)
tma_gemm(const __grid_constant__ CUtensorMap mapA,
         const __grid_constant__ CUtensorMap mapB,
         const float* __restrict__ bias, float* __restrict__ C) {
    extern __shared__ __align__(128) char smt[];
    const uint32_t sb = s2u(smt);
    const int tid = threadIdx.x;
    const int lane = tid & 31;
    const int warp = tid >> 5;
    const int wm = warp >> 2;   // 0..1
    const int wn = warp & 3;    // 0..3
    const int m0 = blockIdx.y * 128;
    const int n0 = blockIdx.x * 128;

    if (tid == 0) {
#pragma unroll
        for (int s = 0; s < TSTAGES; s++) mbar_init(sb + s * 8, 1);
    }
    __syncthreads();

    if (tid == 0) {
#pragma unroll
        for (int p = 0; p < TSTAGES; p++) {
            uint32_t st = sb + 1024 + p * T_STG;
            mbar_expect_tx(sb + p * 8, T_STG);
            tma2d(st,          &mapA, p * TKSTEP, m0, sb + p * 8);
            tma2d(st + T_ASTG, &mapB, p * TKSTEP, n0, sb + p * 8);
        }
    }

    float c[4][4][4];
#pragma unroll
    for (int m = 0; m < 4; m++)
#pragma unroll
        for (int n = 0; n < 4; n++)
#pragma unroll
            for (int r = 0; r < 4; r++) c[m][n][r] = 0.f;

    int phase[TSTAGES] = {0, 0, 0};
    const int kTiles = JOINT_DIM / TKSTEP; // 8

#pragma unroll 1
    for (int kt = 0; kt < kTiles; ++kt) {
        const int s = kt % TSTAGES;
        mbar_wait(sb + s * 8, (uint32_t)phase[s]);
        phase[s] ^= 1;

        const char* aT = smt + 1024 + s * T_STG;
        const char* bT = aT + T_ASTG;

#pragma unroll
        for (int kk = 0; kk < 4; ++kk) {
            uint32_t af[4][4];
            uint32_t bf[2][4];
#pragma unroll
            for (int m = 0; m < 4; m++) {
                int R = wm * 64 + m * 16 + (lane & 15);
                uint32_t off = (uint32_t)(R * 128 + kk * 32 + (lane >> 4) * 16);
                off ^= (uint32_t)((R & 7) << 4);
                uint32_t sa = s2u(aT + off);
                asm volatile("ldmatrix.sync.aligned.m8n8.x4.shared.b16 {%0,%1,%2,%3}, [%4];\n"
                             : "=r"(af[m][0]), "=r"(af[m][1]), "=r"(af[m][2]), "=r"(af[m][3])
                             : "r"(sa));
            }
#pragma unroll
            for (int j = 0; j < 2; j++) {
                int lg = lane >> 3, rr = lane & 7;
                int nrow = wn * 32 + j * 16 + (lg >> 1) * 8 + rr;
                uint32_t off = (uint32_t)(nrow * 128 + kk * 32 + (lg & 1) * 16);
                off ^= (uint32_t)((nrow & 7) << 4);
                uint32_t sa = s2u(bT + off);
                asm volatile("ldmatrix.sync.aligned.m8n8.x4.shared.b16 {%0,%1,%2,%3}, [%4];\n"
                             : "=r"(bf[j][0]), "=r"(bf[j][1]), "=r"(bf[j][2]), "=r"(bf[j][3])
                             : "r"(sa));
            }
#pragma unroll
            for (int m = 0; m < 4; m++) {
#pragma unroll
                for (int n = 0; n < 4; n++) {
                    uint32_t b0 = bf[n >> 1][(n & 1) * 2];
                    uint32_t b1 = bf[n >> 1][(n & 1) * 2 + 1];
                    asm volatile(
                        "mma.sync.aligned.m16n8k16.row.col.f32.f16.f16.f32 "
                        "{%0,%1,%2,%3}, {%4,%5,%6,%7}, {%8,%9}, {%0,%1,%2,%3};\n"
                        : "+f"(c[m][n][0]), "+f"(c[m][n][1]), "+f"(c[m][n][2]), "+f"(c[m][n][3])
                        : "r"(af[m][0]), "r"(af[m][1]), "r"(af[m][2]), "r"(af[m][3]),
                          "r"(b0), "r"(b1));
                }
            }
        }

        __syncthreads();  // all consumers done with stage s
        if (tid == 0 && kt + TSTAGES < kTiles) {
            uint32_t st = sb + 1024 + s * T_STG;
            mbar_expect_tx(sb + s * 8, T_STG);
            tma2d(st,          &mapA, (kt + TSTAGES) * TKSTEP, m0, sb + s * 8);
            tma2d(st + T_ASTG, &mapB, (kt + TSTAGES) * TKSTEP, n0, sb + s * 8);
        }
    }

    // epilogue
    const int mb = m0 + wm * 64;
    const int nb = n0 + wn * 32;
    float2 bb[4];
#pragma unroll
    for (int n = 0; n < 4; n++) {
        int col = nb + n * 8 + (lane & 3) * 2;
        bb[n].x = bias[col];
        bb[n].y = bias[col + 1];
    }
#pragma unroll
    for (int m = 0; m < 4; m++) {
        int row = mb + m * 16 + (lane >> 2);
#pragma unroll
        for (int n = 0; n < 4; n++) {
            int col = nb + n * 8 + (lane & 3) * 2;
            float2 v0 = make_float2(c[m][n][0] + bb[n].x, c[m][n][1] + bb[n].y);
            float2 v1 = make_float2(c[m][n][2] + bb[n].x, c[m][n][3] + bb[n].y);
            __stcs(reinterpret_cast<float2*>(C + (size_t)row * VOCAB + col), v0);
            __stcs(reinterpret_cast<float2*>(C + (size_t)(row + 8) * VOCAB + col), v1);
        }
    }
}

// ---------------------------------------------------------------------------
// Launch
// ---------------------------------------------------------------------------
static void* sym_addr(const void* s) {
    void* p = nullptr;
    cudaGetSymbolAddress(&p, s);
    return p;
}

typedef CUresult (CUDAAPI* PFN_tmEncode)(
    CUtensorMap*, CUtensorMapDataType, cuuint32_t, void*,
    const cuuint64_t*, const cuuint64_t*, const cuuint32_t*, const cuuint32_t*,
    CUtensorMapInterleave, CUtensorMapSwizzle, CUtensorMapL2promotion,
    CUtensorMapFloatOOBfill);

extern "C" void kernel_launch(void* const* d_in, const int* in_sizes, int n_in,
                              void* d_out, int out_size) {
    const float* enc_out = (const float*)d_in[0];
    const float* pred_out = (const float*)d_in[1];
    const float* W_enc = (const float*)d_in[2];
    const float* b_enc = (const float*)d_in[3];
    const float* W_pred = (const float*)d_in[4];
    const float* b_pred = (const float*)d_in[5];
    const float* W_joint = (const float*)d_in[6];
    const float* b_joint = (const float*)d_in[7];
    float* out = (float*)d_out;

    cudaFuncSetAttribute(proj_kernel,
                         cudaFuncAttributeMaxDynamicSharedMemorySize, SMEM_BYTES_L);
    cudaFuncSetAttribute(legacy_gemm,
                         cudaFuncAttributeMaxDynamicSharedMemorySize, SMEM_BYTES_L);
    cudaFuncSetAttribute(tma_gemm,
                         cudaFuncAttributeMaxDynamicSharedMemorySize, TSMEM);

    __half* Amat = (__half*)sym_addr(g_A);
    __half* WjT = (__half*)sym_addr(g_WjT);

    // 1) fp16 conversions + W_joint transpose (one launch)
    convert_kernel<<<2560, 256>>>(enc_out, pred_out, W_enc, W_pred, W_joint);

    // 2) both projections (one launch)
    proj_kernel<<<dim3(JOINT_DIM / 128, 20), 256, SMEM_BYTES_L>>>(b_enc, b_pred);

    // 3) joint tanh -> fp16 A
    joint_tanh_kernel<<<BATCH * TDIM, 256>>>();

    // 4) big GEMM: TMA path if tensor-map encode is available, else fallback
    bool ok = false;
    CUtensorMap mapA, mapB;
    void* fn = nullptr;
    cudaDriverEntryPointQueryResult qr;
    if (cudaGetDriverEntryPoint("cuTensorMapEncodeTiled", &fn,
                                cudaEnableDefault, &qr) == cudaSuccess && fn) {
        PFN_tmEncode encode = (PFN_tmEncode)fn;
        cuuint64_t dimsA[2] = {JOINT_DIM, MROWS};
        cuuint64_t dimsB[2] = {JOINT_DIM, VOCAB};
        cuuint64_t strides[1] = {JOINT_DIM * 2};
        cuuint32_t box[2] = {TKSTEP, 128};
        cuuint32_t es[2] = {1, 1};
        CUresult r1 = encode(&mapA, CU_TENSOR_MAP_DATA_TYPE_FLOAT16, 2, Amat,
                             dimsA, strides, box, es,
                             CU_TENSOR_MAP_INTERLEAVE_NONE,
                             CU_TENSOR_MAP_SWIZZLE_128B,
                             CU_TENSOR_MAP_L2_PROMOTION_L2_128B,
                             CU_TENSOR_MAP_FLOAT_OOB_FILL_NONE);
        CUresult r2 = encode(&mapB, CU_TENSOR_MAP_DATA_TYPE_FLOAT16, 2, WjT,
                             dimsB, strides, box, es,
                             CU_TENSOR_MAP_INTERLEAVE_NONE,
                             CU_TENSOR_MAP_SWIZZLE_128B,
                             CU_TENSOR_MAP_L2_PROMOTION_L2_128B,
                             CU_TENSOR_MAP_FLOAT_OOB_FILL_NONE);
        ok = (r1 == CUDA_SUCCESS) && (r2 == CUDA_SUCCESS);
    }
    if (ok) {
        tma_gemm<<<dim3(VOCAB / 128, MROWS / 128), 256, TSMEM>>>(
            mapA, mapB, b_joint, out);
    } else {
        legacy_gemm<<<dim3(VOCAB / 128, MROWS / 128), 256, SMEM_BYTES_L>>>(
            b_joint, out);
    }
}

// round 9
// speedup vs baseline: 1.3569x; 1.3569x over previous
#include <cuda_runtime.h>
#include <cuda.h>
#include <cuda_fp16.h>
#include <cstdint>

// ---------------------------------------------------------------------------
// Problem dims (fixed by the dataset)
// ---------------------------------------------------------------------------
#define BATCH 8
#define TDIM 256
#define UDIM 64
#define ENC_DIM 512
#define PRED_DIM 640
#define JOINT_DIM 512
#define VOCAB 1024
#define MROWS (BATCH * TDIM * UDIM) // 131072

// ---------------------------------------------------------------------------
// Scratch (static __device__ arrays -- allocation-free per harness rules)
// ---------------------------------------------------------------------------
__device__ __align__(128) __half g_encH[BATCH * TDIM * ENC_DIM];
__device__ __align__(128) __half g_predH[BATCH * UDIM * PRED_DIM];
__device__ __align__(128) __half g_WencH[ENC_DIM * JOINT_DIM];
__device__ __align__(128) __half g_WpredH[PRED_DIM * JOINT_DIM];
__device__ __align__(128) __half g_WjH[JOINT_DIM * VOCAB];        // [K,V] (fallback)
__device__ __align__(128) __half g_WjT[VOCAB * JOINT_DIM];        // [V,K] (TMA path)
__device__ __align__(128) float  g_encP[BATCH * TDIM * JOINT_DIM];
__device__ __align__(128) float  g_predP[BATCH * UDIM * JOINT_DIM];
__device__ __align__(128) __half g_A[(size_t)MROWS * JOINT_DIM];  // 134 MB

// ---------------------------------------------------------------------------
// Helpers
// ---------------------------------------------------------------------------
__device__ __forceinline__ float tanh_ap(float x) {
    float y;
    asm("tanh.approx.f32 %0, %1;" : "=f"(y) : "f"(x));
    return y;
}
__device__ __forceinline__ uint32_t s2u(const void* p) {
    return (uint32_t)__cvta_generic_to_shared(p);
}
__device__ __forceinline__ void cpa16(uint32_t sa, const void* g) {
    asm volatile("cp.async.cg.shared.global [%0], [%1], 16;\n" :: "r"(sa), "l"(g));
}
__device__ __forceinline__ void mbar_init(uint32_t a, uint32_t cnt) {
    asm volatile("mbarrier.init.shared.b64 [%0], %1;" :: "r"(a), "r"(cnt) : "memory");
}
__device__ __forceinline__ void mbar_expect_tx(uint32_t a, uint32_t bytes) {
    asm volatile("mbarrier.arrive.expect_tx.shared.b64 _, [%0], %1;"
                 :: "r"(a), "r"(bytes) : "memory");
}
__device__ __forceinline__ void mbar_wait(uint32_t a, uint32_t parity) {
    asm volatile(
        "{\n\t.reg .pred P1;\n\t"
        "LAB_WAIT_%=:\n\t"
        "mbarrier.try_wait.parity.acquire.cta.shared::cta.b64 P1, [%0], %1, 0x989680;\n\t"
        "@P1 bra.uni LAB_DONE_%=;\n\t"
        "bra.uni LAB_WAIT_%=;\n\t"
        "LAB_DONE_%=:\n\t}"
        :: "r"(a), "r"(parity) : "memory");
}
__device__ __forceinline__ void tma2d(uint32_t saddr, const CUtensorMap* map,
                                      int x, int y, uint32_t mbar) {
    asm volatile(
        "cp.async.bulk.tensor.2d.shared::cta.global.tile.mbarrier::complete_tx::bytes "
        "[%0], [%1, {%2, %3}], [%4];"
        :: "r"(saddr), "l"(map), "r"(x), "r"(y), "r"(mbar) : "memory");
}

// ---------------------------------------------------------------------------
// Kernel 1: fp32 -> fp16 conversion + W_joint transpose (region-dispatched)
// ---------------------------------------------------------------------------
__global__ void convert_kernel(const float* __restrict__ enc,
                               const float* __restrict__ pred,
                               const float* __restrict__ we,
                               const float* __restrict__ wp,
                               const float* __restrict__ wj) {
    __shared__ float t[64][65];
    int blk = blockIdx.x;
    int tid = threadIdx.x;
    if (blk >= 2432) {
        int tile = blk - 2432;
        int v0 = (tile & 15) * 64;
        int j0 = (tile >> 4) * 64;
#pragma unroll
        for (int i = 0; i < 16; i++) {
            int e = i * 256 + tid;
            int j = e >> 6, v = e & 63;
            t[j][v] = wj[(size_t)(j0 + j) * VOCAB + v0 + v];
        }
        __syncthreads();
#pragma unroll
        for (int i = 0; i < 16; i++) {
            int e = i * 256 + tid;
            int v = e >> 6, j = e & 63;
            g_WjT[(size_t)(v0 + v) * JOINT_DIM + j0 + j] = __float2half(t[j][v]);
        }
        return;
    }
    const float* src;
    __half* dst;
    int lb;
    if (blk < 1024)      { src = enc;  dst = g_encH;   lb = blk; }
    else if (blk < 1344) { src = pred; dst = g_predH;  lb = blk - 1024; }
    else if (blk < 1600) { src = we;   dst = g_WencH;  lb = blk - 1344; }
    else if (blk < 1920) { src = wp;   dst = g_WpredH; lb = blk - 1600; }
    else                 { src = wj;   dst = g_WjH;    lb = blk - 1920; }
    int idx = lb * 1024 + tid * 4;
    float4 v = *reinterpret_cast<const float4*>(src + idx);
    __half2 h0 = __floats2half2_rn(v.x, v.y);
    __half2 h1 = __floats2half2_rn(v.z, v.w);
    uint2 o;
    o.x = *reinterpret_cast<uint32_t*>(&h0);
    o.y = *reinterpret_cast<uint32_t*>(&h1);
    *reinterpret_cast<uint2*>(dst + idx) = o;
}

// ---------------------------------------------------------------------------
// Shared HGEMM body (cp.async path) for projections + legacy fallback.
// ---------------------------------------------------------------------------
#define KSTEP 32
#define STAGES 3
#define A_LD 40
#define B_LD 136
#define A_STGL (128 * A_LD)
#define B_STGL (KSTEP * B_LD)
#define SMEM_BYTES_L ((STAGES * A_STGL + STAGES * B_STGL) * 2)

__device__ __forceinline__ void load_tile(const __half* __restrict__ A,
                                          const __half* __restrict__ Bm,
                                          int K, int N, int m0, int n0, int kt,
                                          __half* aS, __half* bS, int tid) {
    int k0 = kt * KSTEP;
#pragma unroll
    for (int i = 0; i < 2; i++) {
        int idx = tid + i * 256;
        int ar = idx >> 2, ac = (idx & 3) * 8;
        cpa16(s2u(aS + ar * A_LD + ac), A + (size_t)(m0 + ar) * K + k0 + ac);
        int br = idx >> 4, bc = (idx & 15) * 8;
        cpa16(s2u(bS + br * B_LD + bc), Bm + (size_t)(k0 + br) * N + n0 + bc);
    }
}

__device__ __forceinline__ void hgemm_body(const __half* __restrict__ A,
                                           const __half* __restrict__ Bm,
                                           const float* __restrict__ bias,
                                           float* __restrict__ C,
                                           int K, int N, int m0, int n0,
                                           __half* smemBuf) {
    __half* aS = smemBuf;
    __half* bS = smemBuf + STAGES * A_STGL;
    const int tid = threadIdx.x;
    const int lane = tid & 31;
    const int warp = tid >> 5;
    const int wm = warp >> 2;
    const int wn = warp & 3;
    const int kTiles = K / KSTEP;

#pragma unroll
    for (int p = 0; p < STAGES - 1; p++) {
        load_tile(A, Bm, K, N, m0, n0, p, aS + p * A_STGL, bS + p * B_STGL, tid);
        asm volatile("cp.async.commit_group;\n");
    }

    float c[4][4][4];
#pragma unroll
    for (int m = 0; m < 4; m++)
#pragma unroll
        for (int n = 0; n < 4; n++)
#pragma unroll
            for (int r = 0; r < 4; r++) c[m][n][r] = 0.f;

    for (int kt = 0; kt < kTiles; ++kt) {
        asm volatile("cp.async.wait_group %0;\n" :: "n"(STAGES - 2));
        __syncthreads();

        int nx = kt + STAGES - 1;
        if (nx < kTiles)
            load_tile(A, Bm, K, N, m0, n0, nx,
                      aS + (nx % STAGES) * A_STGL, bS + (nx % STAGES) * B_STGL, tid);
        asm volatile("cp.async.commit_group;\n");

        const __half* a = aS + (kt % STAGES) * A_STGL;
        const __half* b = bS + (kt % STAGES) * B_STGL;

#pragma unroll
        for (int kk = 0; kk < 2; ++kk) {
            uint32_t af[4][4];
            uint32_t bf[2][4];
#pragma unroll
            for (int m = 0; m < 4; m++) {
                const __half* p = a + (wm * 64 + m * 16 + (lane & 15)) * A_LD
                                    + kk * 16 + (lane >> 4) * 8;
                uint32_t sa = s2u(p);
                asm volatile("ldmatrix.sync.aligned.m8n8.x4.shared.b16 {%0,%1,%2,%3}, [%4];\n"
                             : "=r"(af[m][0]), "=r"(af[m][1]), "=r"(af[m][2]), "=r"(af[m][3])
                             : "r"(sa));
            }
#pragma unroll
            for (int g = 0; g < 2; g++) {
                const __half* p = b + (kk * 16 + (lane & 15)) * B_LD
                                    + wn * 32 + g * 16 + (lane >> 4) * 8;
                uint32_t sa = s2u(p);
                asm volatile("ldmatrix.sync.aligned.m8n8.x4.trans.shared.b16 {%0,%1,%2,%3}, [%4];\n"
                             : "=r"(bf[g][0]), "=r"(bf[g][1]), "=r"(bf[g][2]), "=r"(bf[g][3])
                             : "r"(sa));
            }
#pragma unroll
            for (int m = 0; m < 4; m++) {
#pragma unroll
                for (int n = 0; n < 4; n++) {
                    uint32_t b0 = bf[n >> 1][(n & 1) * 2];
                    uint32_t b1 = bf[n >> 1][(n & 1) * 2 + 1];
                    asm volatile(
                        "mma.sync.aligned.m16n8k16.row.col.f32.f16.f16.f32 "
                        "{%0,%1,%2,%3}, {%4,%5,%6,%7}, {%8,%9}, {%0,%1,%2,%3};\n"
                        : "+f"(c[m][n][0]), "+f"(c[m][n][1]), "+f"(c[m][n][2]), "+f"(c[m][n][3])
                        : "r"(af[m][0]), "r"(af[m][1]), "r"(af[m][2]), "r"(af[m][3]),
                          "r"(b0), "r"(b1));
                }
            }
        }
    }

    const int mb = m0 + wm * 64;
    const int nb = n0 + wn * 32;
    float2 bb[4];
#pragma unroll
    for (int n = 0; n < 4; n++) {
        int col = nb + n * 8 + (lane & 3) * 2;
        bb[n].x = bias[col];
        bb[n].y = bias[col + 1];
    }
#pragma unroll
    for (int m = 0; m < 4; m++) {
        int row = mb + m * 16 + (lane >> 2);
#pragma unroll
        for (int n = 0; n < 4; n++) {
            int col = nb + n * 8 + (lane & 3) * 2;
            float2 v0 = make_float2(c[m][n][0] + bb[n].x, c[m][n][1] + bb[n].y);
            float2 v1 = make_float2(c[m][n][2] + bb[n].x, c[m][n][3] + bb[n].y);
            __stcs(reinterpret_cast<float2*>(C + (size_t)row * N + col), v0);
            __stcs(reinterpret_cast<float2*>(C + (size_t)(row + 8) * N + col), v1);
        }
    }
}

// Kernel 2: both projections fused into one launch (grid y: 16 enc + 4 pred)
__global__ void __launch_bounds__(256, 2)
proj_kernel(const float* __restrict__ b_enc, const float* __restrict__ b_pred) {
    extern __shared__ __half smemBuf[];
    int y = blockIdx.y;
    if (y < 16)
        hgemm_body(g_encH, g_WencH, b_enc, g_encP, ENC_DIM, JOINT_DIM,
                   y * 128, blockIdx.x * 128, smemBuf);
    else
        hgemm_body(g_predH, g_WpredH, b_pred, g_predP, PRED_DIM, JOINT_DIM,
                   (y - 16) * 128, blockIdx.x * 128, smemBuf);
}

// Fallback big GEMM (cp.async path) -- only used if TMA setup fails
__global__ void __launch_bounds__(256, 2)
legacy_gemm(const float* __restrict__ bias, float* __restrict__ C) {
    extern __shared__ __half smemBuf[];
    hgemm_body(g_A, g_WjH, bias, C, JOINT_DIM, VOCAB,
               blockIdx.y * 128, blockIdx.x * 128, smemBuf);
}

// ---------------------------------------------------------------------------
// Kernel 3: joint = tanh(enc_p[b,t,:] + pred_p[b,u,:]) -> fp16 A matrix.
// Register-resident enc slice, no smem, no sync.
// ---------------------------------------------------------------------------
__global__ void __launch_bounds__(256) joint_tanh_kernel() {
    const int bt = blockIdx.x;          // 0..2047
    const int tid = threadIdx.x;
    const int b = bt >> 8;
    const int j8 = (tid & 63) * 8;      // fixed 8-col slice
    const int ug = tid >> 6;            // 0..3

    const float4* encRow = reinterpret_cast<const float4*>(
        g_encP + (size_t)bt * JOINT_DIM + j8);
    const float4 e0 = encRow[0];
    const float4 e1 = encRow[1];

    const float* predBase = g_predP + (size_t)(b * UDIM) * JOINT_DIM + j8;
    __half* outBase = g_A + (size_t)bt * UDIM * JOINT_DIM + j8;

#pragma unroll 4
    for (int i = 0; i < 16; i++) {
        int u = i * 4 + ug;
        const float4* pp = reinterpret_cast<const float4*>(
            predBase + (size_t)u * JOINT_DIM);
        float4 p0 = pp[0], p1 = pp[1];
        __half2 h0 = __floats2half2_rn(tanh_ap(e0.x + p0.x), tanh_ap(e0.y + p0.y));
        __half2 h1 = __floats2half2_rn(tanh_ap(e0.z + p0.z), tanh_ap(e0.w + p0.w));
        __half2 h2 = __floats2half2_rn(tanh_ap(e1.x + p1.x), tanh_ap(e1.y + p1.y));
        __half2 h3 = __floats2half2_rn(tanh_ap(e1.z + p1.z), tanh_ap(e1.w + p1.w));
        uint4 o;
        o.x = *reinterpret_cast<uint32_t*>(&h0);
        o.y = *reinterpret_cast<uint32_t*>(&h1);
        o.z = *reinterpret_cast<uint32_t*>(&h2);
        o.w = *reinterpret_cast<uint32_t*>(&h3);
        *reinterpret_cast<uint4*>(outBase + (size_t)u * JOINT_DIM) = o;
    }
}

// ---------------------------------------------------------------------------
// Kernel 4: TMA big GEMM v2. CTA 128x256, 8 warps, warp tile 64x64.
// KSTEP 64, 3-stage TMA+mbarrier pipeline (round-5 proven sync scheme),
// SW128 swizzle, 1 CTA/SM (145 KB smem).
// ---------------------------------------------------------------------------
#define TKSTEP 64
#define TSTAGES 3
#define T_ASTG 16384                      // A: 128 rows x 128B
#define T_BSTG 32768                      // B: 256 rows x 128B
#define T_STG  (T_ASTG + T_BSTG)          // 48 KB per stage
#define TSMEM  (1024 + TSTAGES * T_STG)   // 148480 B

__global__ void __launch_bounds__(256, 1)
tma_gemm(const __grid_constant__ CUtensorMap mapA,
         const __grid_constant__ CUtensorMap mapB,
         const float* __restrict__ bias, float* __restrict__ C) {
    extern __shared__ __align__(128) char smt[];
    const uint32_t sb = s2u(smt);
    const int tid = threadIdx.x;
    const int lane = tid & 31;
    const int warp = tid >> 5;
    const int wm = warp >> 2;   // 0..1 -> 64-row group
    const int wn = warp & 3;    // 0..3 -> 64-col group
    const int m0 = blockIdx.y * 128;
    const int n0 = blockIdx.x * 256;

    if (tid == 0) {
#pragma unroll
        for (int s = 0; s < TSTAGES; s++) mbar_init(sb + s * 8, 1);
    }
    __syncthreads();

    if (tid == 0) {
#pragma unroll
        for (int p = 0; p < TSTAGES; p++) {
            uint32_t st = sb + 1024 + p * T_STG;
            mbar_expect_tx(sb + p * 8, T_STG);
            tma2d(st,          &mapA, p * TKSTEP, m0, sb + p * 8);
            tma2d(st + T_ASTG, &mapB, p * TKSTEP, n0, sb + p * 8);
        }
    }

    float c[4][8][4];
#pragma unroll
    for (int m = 0; m < 4; m++)
#pragma unroll
        for (int n = 0; n < 8; n++)
#pragma unroll
            for (int r = 0; r < 4; r++) c[m][n][r] = 0.f;

    int phase[TSTAGES] = {0, 0, 0};
    const int kTiles = JOINT_DIM / TKSTEP; // 8

#pragma unroll 1
    for (int kt = 0; kt < kTiles; ++kt) {
        const int s = kt % TSTAGES;
        mbar_wait(sb + s * 8, (uint32_t)phase[s]);
        phase[s] ^= 1;

        const char* aT = smt + 1024 + s * T_STG;
        const char* bT = aT + T_ASTG;

#pragma unroll
        for (int kk = 0; kk < 4; ++kk) {
            uint32_t af[4][4];
            uint32_t bf[4][4];
#pragma unroll
            for (int m = 0; m < 4; m++) {
                int R = wm * 64 + m * 16 + (lane & 15);
                uint32_t off = (uint32_t)(R * 128 + kk * 32 + (lane >> 4) * 16);
                off ^= (uint32_t)((R & 7) << 4);
                uint32_t sa = s2u(aT + off);
                asm volatile("ldmatrix.sync.aligned.m8n8.x4.shared.b16 {%0,%1,%2,%3}, [%4];\n"
                             : "=r"(af[m][0]), "=r"(af[m][1]), "=r"(af[m][2]), "=r"(af[m][3])
                             : "r"(sa));
            }
#pragma unroll
            for (int j = 0; j < 4; j++) {
                int lg = lane >> 3, rr = lane & 7;
                int nrow = wn * 64 + j * 16 + (lg >> 1) * 8 + rr;
                uint32_t off = (uint32_t)(nrow * 128 + kk * 32 + (lg & 1) * 16);
                off ^= (uint32_t)((nrow & 7) << 4);
                uint32_t sa = s2u(bT + off);
                asm volatile("ldmatrix.sync.aligned.m8n8.x4.shared.b16 {%0,%1,%2,%3}, [%4];\n"
                             : "=r"(bf[j][0]), "=r"(bf[j][1]), "=r"(bf[j][2]), "=r"(bf[j][3])
                             : "r"(sa));
            }
#pragma unroll
            for (int m = 0; m < 4; m++) {
#pragma unroll
                for (int n = 0; n < 8; n++) {
                    uint32_t b0 = bf[n >> 1][(n & 1) * 2];
                    uint32_t b1 = bf[n >> 1][(n & 1) * 2 + 1];
                    asm volatile(
                        "mma.sync.aligned.m16n8k16.row.col.f32.f16.f16.f32 "
                        "{%0,%1,%2,%3}, {%4,%5,%6,%7}, {%8,%9}, {%0,%1,%2,%3};\n"
                        : "+f"(c[m][n][0]), "+f"(c[m][n][1]), "+f"(c[m][n][2]), "+f"(c[m][n][3])
                        : "r"(af[m][0]), "r"(af[m][1]), "r"(af[m][2]), "r"(af[m][3]),
                          "r"(b0), "r"(b1));
                }
            }
        }

        __syncthreads();  // all consumers done with stage s
        if (tid == 0 && kt + TSTAGES < kTiles) {
            uint32_t st = sb + 1024 + s * T_STG;
            mbar_expect_tx(sb + s * 8, T_STG);
            tma2d(st,          &mapA, (kt + TSTAGES) * TKSTEP, m0, sb + s * 8);
            tma2d(st + T_ASTG, &mapB, (kt + TSTAGES) * TKSTEP, n0, sb + s * 8);
        }
    }

    // epilogue
    const int mb = m0 + wm * 64;
    const int nb = n0 + wn * 64;
    float2 bb[8];
#pragma unroll
    for (int n = 0; n < 8; n++) {
        int col = nb + n * 8 + (lane & 3) * 2;
        bb[n].x = bias[col];
        bb[n].y = bias[col + 1];
    }
#pragma unroll
    for (int m = 0; m < 4; m++) {
        int row = mb + m * 16 + (lane >> 2);
#pragma unroll
        for (int n = 0; n < 8; n++) {
            int col = nb + n * 8 + (lane & 3) * 2;
            float2 v0 = make_float2(c[m][n][0] + bb[n].x, c[m][n][1] + bb[n].y);
            float2 v1 = make_float2(c[m][n][2] + bb[n].x, c[m][n][3] + bb[n].y);
            __stcs(reinterpret_cast<float2*>(C + (size_t)row * VOCAB + col), v0);
            __stcs(reinterpret_cast<float2*>(C + (size_t)(row + 8) * VOCAB + col), v1);
        }
    }
}

// ---------------------------------------------------------------------------
// Launch
// ---------------------------------------------------------------------------
static void* sym_addr(const void* s) {
    void* p = nullptr;
    cudaGetSymbolAddress(&p, s);
    return p;
}

typedef CUresult (CUDAAPI* PFN_tmEncode)(
    CUtensorMap*, CUtensorMapDataType, cuuint32_t, void*,
    const cuuint64_t*, const cuuint64_t*, const cuuint32_t*, const cuuint32_t*,
    CUtensorMapInterleave, CUtensorMapSwizzle, CUtensorMapL2promotion,
    CUtensorMapFloatOOBfill);

extern "C" void kernel_launch(void* const* d_in, const int* in_sizes, int n_in,
                              void* d_out, int out_size) {
    const float* enc_out = (const float*)d_in[0];
    const float* pred_out = (const float*)d_in[1];
    const float* W_enc = (const float*)d_in[2];
    const float* b_enc = (const float*)d_in[3];
    const float* W_pred = (const float*)d_in[4];
    const float* b_pred = (const float*)d_in[5];
    const float* W_joint = (const float*)d_in[6];
    const float* b_joint = (const float*)d_in[7];
    float* out = (float*)d_out;

    cudaFuncSetAttribute(proj_kernel,
                         cudaFuncAttributeMaxDynamicSharedMemorySize, SMEM_BYTES_L);
    cudaFuncSetAttribute(legacy_gemm,
                         cudaFuncAttributeMaxDynamicSharedMemorySize, SMEM_BYTES_L);
    cudaFuncSetAttribute(tma_gemm,
                         cudaFuncAttributeMaxDynamicSharedMemorySize, TSMEM);

    __half* Amat = (__half*)sym_addr(g_A);
    __half* WjT = (__half*)sym_addr(g_WjT);

    // 1) fp16 conversions + W_joint transpose (one launch)
    convert_kernel<<<2560, 256>>>(enc_out, pred_out, W_enc, W_pred, W_joint);

    // 2) both projections (one launch)
    proj_kernel<<<dim3(JOINT_DIM / 128, 20), 256, SMEM_BYTES_L>>>(b_enc, b_pred);

    // 3) joint tanh -> fp16 A
    joint_tanh_kernel<<<BATCH * TDIM, 256>>>();

    // 4) big GEMM: TMA path if tensor-map encode is available, else fallback
    bool ok = false;
    CUtensorMap mapA, mapB;
    void* fn = nullptr;
    cudaDriverEntryPointQueryResult qr;
    if (cudaGetDriverEntryPoint("cuTensorMapEncodeTiled", &fn,
                                cudaEnableDefault, &qr) == cudaSuccess && fn) {
        PFN_tmEncode encode = (PFN_tmEncode)fn;
        cuuint64_t dimsA[2] = {JOINT_DIM, MROWS};
        cuuint64_t dimsB[2] = {JOINT_DIM, VOCAB};
        cuuint64_t strides[1] = {JOINT_DIM * 2};
        cuuint32_t boxA[2] = {TKSTEP, 128};
        cuuint32_t boxB[2] = {TKSTEP, 256};
        cuuint32_t es[2] = {1, 1};
        CUresult r1 = encode(&mapA, CU_TENSOR_MAP_DATA_TYPE_FLOAT16, 2, Amat,
                             dimsA, strides, boxA, es,
                             CU_TENSOR_MAP_INTERLEAVE_NONE,
                             CU_TENSOR_MAP_SWIZZLE_128B,
                             CU_TENSOR_MAP_L2_PROMOTION_L2_128B,
                             CU_TENSOR_MAP_FLOAT_OOB_FILL_NONE);
        CUresult r2 = encode(&mapB, CU_TENSOR_MAP_DATA_TYPE_FLOAT16, 2, WjT,
                             dimsB, strides, boxB, es,
                             CU_TENSOR_MAP_INTERLEAVE_NONE,
                             CU_TENSOR_MAP_SWIZZLE_128B,
                             CU_TENSOR_MAP_L2_PROMOTION_L2_128B,
                             CU_TENSOR_MAP_FLOAT_OOB_FILL_NONE);
        ok = (r1 == CUDA_SUCCESS) && (r2 == CUDA_SUCCESS);
    }
    if (ok) {
        tma_gemm<<<dim3(VOCAB / 256, MROWS / 128), 256, TSMEM>>>(
            mapA, mapB, b_joint, out);
    } else {
        legacy_gemm<<<dim3(VOCAB / 128, MROWS / 128), 256, SMEM_BYTES_L>>>(
            b_joint, out);
    }
}

// round 10
// speedup vs baseline: 1.5332x; 1.1299x over previous
#include <cuda_runtime.h>
#include <cuda.h>
#include <cuda_fp16.h>
#include <cstdint>

// ---------------------------------------------------------------------------
// Problem dims (fixed by the dataset)
// ---------------------------------------------------------------------------
#define BATCH 8
#define TDIM 256
#define UDIM 64
#define ENC_DIM 512
#define PRED_DIM 640
#define JOINT_DIM 512
#define VOCAB 1024
#define MROWS (BATCH * TDIM * UDIM) // 131072

// ---------------------------------------------------------------------------
// Scratch (static __device__ arrays -- allocation-free per harness rules)
// ---------------------------------------------------------------------------
__device__ __align__(128) __half g_encH[BATCH * TDIM * ENC_DIM];
__device__ __align__(128) __half g_predH[BATCH * UDIM * PRED_DIM];
__device__ __align__(128) __half g_WencH[ENC_DIM * JOINT_DIM];
__device__ __align__(128) __half g_WpredH[PRED_DIM * JOINT_DIM];
__device__ __align__(128) __half g_WjH[JOINT_DIM * VOCAB];        // [K,V] (fallback)
__device__ __align__(128) __half g_WjT[VOCAB * JOINT_DIM];        // [V,K] (TMA path)
__device__ __align__(128) float  g_encP[BATCH * TDIM * JOINT_DIM];
__device__ __align__(128) float  g_predP[BATCH * UDIM * JOINT_DIM];
__device__ __align__(128) __half g_A[(size_t)MROWS * JOINT_DIM];  // 134 MB

// ---------------------------------------------------------------------------
// Helpers
// ---------------------------------------------------------------------------
__device__ __forceinline__ float tanh_ap(float x) {
    float y;
    asm("tanh.approx.f32 %0, %1;" : "=f"(y) : "f"(x));
    return y;
}
__device__ __forceinline__ uint32_t s2u(const void* p) {
    return (uint32_t)__cvta_generic_to_shared(p);
}
__device__ __forceinline__ void cpa16(uint32_t sa, const void* g) {
    asm volatile("cp.async.cg.shared.global [%0], [%1], 16;\n" :: "r"(sa), "l"(g));
}
__device__ __forceinline__ void mbar_init(uint32_t a, uint32_t cnt) {
    asm volatile("mbarrier.init.shared.b64 [%0], %1;" :: "r"(a), "r"(cnt) : "memory");
}
__device__ __forceinline__ void mbar_expect_tx(uint32_t a, uint32_t bytes) {
    asm volatile("mbarrier.arrive.expect_tx.shared.b64 _, [%0], %1;"
                 :: "r"(a), "r"(bytes) : "memory");
}
__device__ __forceinline__ void mbar_wait(uint32_t a, uint32_t parity) {
    asm volatile(
        "{\n\t.reg .pred P1;\n\t"
        "LAB_WAIT_%=:\n\t"
        "mbarrier.try_wait.parity.acquire.cta.shared::cta.b64 P1, [%0], %1, 0x989680;\n\t"
        "@P1 bra.uni LAB_DONE_%=;\n\t"
        "bra.uni LAB_WAIT_%=;\n\t"
        "LAB_DONE_%=:\n\t}"
        :: "r"(a), "r"(parity) : "memory");
}
__device__ __forceinline__ void tma2d(uint32_t saddr, const CUtensorMap* map,
                                      int x, int y, uint32_t mbar) {
    asm volatile(
        "cp.async.bulk.tensor.2d.shared::cta.global.tile.mbarrier::complete_tx::bytes "
        "[%0], [%1, {%2, %3}], [%4];"
        :: "r"(saddr), "l"(map), "r"(x), "r"(y), "r"(mbar) : "memory");
}

// ---------------------------------------------------------------------------
// Kernel 1: fp32 -> fp16 conversion + W_joint transpose (region-dispatched)
// ---------------------------------------------------------------------------
__global__ void convert_kernel(const float* __restrict__ enc,
                               const float* __restrict__ pred,
                               const float* __restrict__ we,
                               const float* __restrict__ wp,
                               const float* __restrict__ wj) {
    __shared__ float t[64][65];
    int blk = blockIdx.x;
    int tid = threadIdx.x;
    if (blk >= 2432) {
        int tile = blk - 2432;
        int v0 = (tile & 15) * 64;
        int j0 = (tile >> 4) * 64;
#pragma unroll
        for (int i = 0; i < 16; i++) {
            int e = i * 256 + tid;
            int j = e >> 6, v = e & 63;
            t[j][v] = wj[(size_t)(j0 + j) * VOCAB + v0 + v];
        }
        __syncthreads();
#pragma unroll
        for (int i = 0; i < 16; i++) {
            int e = i * 256 + tid;
            int v = e >> 6, j = e & 63;
            g_WjT[(size_t)(v0 + v) * JOINT_DIM + j0 + j] = __float2half(t[j][v]);
        }
        return;
    }
    const float* src;
    __half* dst;
    int lb;
    if (blk < 1024)      { src = enc;  dst = g_encH;   lb = blk; }
    else if (blk < 1344) { src = pred; dst = g_predH;  lb = blk - 1024; }
    else if (blk < 1600) { src = we;   dst = g_WencH;  lb = blk - 1344; }
    else if (blk < 1920) { src = wp;   dst = g_WpredH; lb = blk - 1600; }
    else                 { src = wj;   dst = g_WjH;    lb = blk - 1920; }
    int idx = lb * 1024 + tid * 4;
    float4 v = *reinterpret_cast<const float4*>(src + idx);
    __half2 h0 = __floats2half2_rn(v.x, v.y);
    __half2 h1 = __floats2half2_rn(v.z, v.w);
    uint2 o;
    o.x = *reinterpret_cast<uint32_t*>(&h0);
    o.y = *reinterpret_cast<uint32_t*>(&h1);
    *reinterpret_cast<uint2*>(dst + idx) = o;
}

// ---------------------------------------------------------------------------
// Shared HGEMM body (cp.async path) for projections + legacy fallback.
// ---------------------------------------------------------------------------
#define KSTEP 32
#define STAGES 3
#define A_LD 40
#define B_LD 136
#define A_STGL (128 * A_LD)
#define B_STGL (KSTEP * B_LD)
#define SMEM_BYTES_L ((STAGES * A_STGL + STAGES * B_STGL) * 2)

__device__ __forceinline__ void load_tile(const __half* __restrict__ A,
                                          const __half* __restrict__ Bm,
                                          int K, int N, int m0, int n0, int kt,
                                          __half* aS, __half* bS, int tid) {
    int k0 = kt * KSTEP;
#pragma unroll
    for (int i = 0; i < 2; i++) {
        int idx = tid + i * 256;
        int ar = idx >> 2, ac = (idx & 3) * 8;
        cpa16(s2u(aS + ar * A_LD + ac), A + (size_t)(m0 + ar) * K + k0 + ac);
        int br = idx >> 4, bc = (idx & 15) * 8;
        cpa16(s2u(bS + br * B_LD + bc), Bm + (size_t)(k0 + br) * N + n0 + bc);
    }
}

__device__ __forceinline__ void hgemm_body(const __half* __restrict__ A,
                                           const __half* __restrict__ Bm,
                                           const float* __restrict__ bias,
                                           float* __restrict__ C,
                                           int K, int N, int m0, int n0,
                                           __half* smemBuf) {
    __half* aS = smemBuf;
    __half* bS = smemBuf + STAGES * A_STGL;
    const int tid = threadIdx.x;
    const int lane = tid & 31;
    const int warp = tid >> 5;
    const int wm = warp >> 2;
    const int wn = warp & 3;
    const int kTiles = K / KSTEP;

#pragma unroll
    for (int p = 0; p < STAGES - 1; p++) {
        load_tile(A, Bm, K, N, m0, n0, p, aS + p * A_STGL, bS + p * B_STGL, tid);
        asm volatile("cp.async.commit_group;\n");
    }

    float c[4][4][4];
#pragma unroll
    for (int m = 0; m < 4; m++)
#pragma unroll
        for (int n = 0; n < 4; n++)
#pragma unroll
            for (int r = 0; r < 4; r++) c[m][n][r] = 0.f;

    for (int kt = 0; kt < kTiles; ++kt) {
        asm volatile("cp.async.wait_group %0;\n" :: "n"(STAGES - 2));
        __syncthreads();

        int nx = kt + STAGES - 1;
        if (nx < kTiles)
            load_tile(A, Bm, K, N, m0, n0, nx,
                      aS + (nx % STAGES) * A_STGL, bS + (nx % STAGES) * B_STGL, tid);
        asm volatile("cp.async.commit_group;\n");

        const __half* a = aS + (kt % STAGES) * A_STGL;
        const __half* b = bS + (kt % STAGES) * B_STGL;

#pragma unroll
        for (int kk = 0; kk < 2; ++kk) {
            uint32_t af[4][4];
            uint32_t bf[2][4];
#pragma unroll
            for (int m = 0; m < 4; m++) {
                const __half* p = a + (wm * 64 + m * 16 + (lane & 15)) * A_LD
                                    + kk * 16 + (lane >> 4) * 8;
                uint32_t sa = s2u(p);
                asm volatile("ldmatrix.sync.aligned.m8n8.x4.shared.b16 {%0,%1,%2,%3}, [%4];\n"
                             : "=r"(af[m][0]), "=r"(af[m][1]), "=r"(af[m][2]), "=r"(af[m][3])
                             : "r"(sa));
            }
#pragma unroll
            for (int g = 0; g < 2; g++) {
                const __half* p = b + (kk * 16 + (lane & 15)) * B_LD
                                    + wn * 32 + g * 16 + (lane >> 4) * 8;
                uint32_t sa = s2u(p);
                asm volatile("ldmatrix.sync.aligned.m8n8.x4.trans.shared.b16 {%0,%1,%2,%3}, [%4];\n"
                             : "=r"(bf[g][0]), "=r"(bf[g][1]), "=r"(bf[g][2]), "=r"(bf[g][3])
                             : "r"(sa));
            }
#pragma unroll
            for (int m = 0; m < 4; m++) {
#pragma unroll
                for (int n = 0; n < 4; n++) {
                    uint32_t b0 = bf[n >> 1][(n & 1) * 2];
                    uint32_t b1 = bf[n >> 1][(n & 1) * 2 + 1];
                    asm volatile(
                        "mma.sync.aligned.m16n8k16.row.col.f32.f16.f16.f32 "
                        "{%0,%1,%2,%3}, {%4,%5,%6,%7}, {%8,%9}, {%0,%1,%2,%3};\n"
                        : "+f"(c[m][n][0]), "+f"(c[m][n][1]), "+f"(c[m][n][2]), "+f"(c[m][n][3])
                        : "r"(af[m][0]), "r"(af[m][1]), "r"(af[m][2]), "r"(af[m][3]),
                          "r"(b0), "r"(b1));
                }
            }
        }
    }

    const int mb = m0 + wm * 64;
    const int nb = n0 + wn * 32;
    float2 bb[4];
#pragma unroll
    for (int n = 0; n < 4; n++) {
        int col = nb + n * 8 + (lane & 3) * 2;
        bb[n].x = bias[col];
        bb[n].y = bias[col + 1];
    }
#pragma unroll
    for (int m = 0; m < 4; m++) {
        int row = mb + m * 16 + (lane >> 2);
#pragma unroll
        for (int n = 0; n < 4; n++) {
            int col = nb + n * 8 + (lane & 3) * 2;
            float2 v0 = make_float2(c[m][n][0] + bb[n].x, c[m][n][1] + bb[n].y);
            float2 v1 = make_float2(c[m][n][2] + bb[n].x, c[m][n][3] + bb[n].y);
            __stcs(reinterpret_cast<float2*>(C + (size_t)row * N + col), v0);
            __stcs(reinterpret_cast<float2*>(C + (size_t)(row + 8) * N + col), v1);
        }
    }
}

// Kernel 2: both projections fused into one launch (grid y: 16 enc + 4 pred)
__global__ void __launch_bounds__(256, 2)
proj_kernel(const float* __restrict__ b_enc, const float* __restrict__ b_pred) {
    extern __shared__ __half smemBuf[];
    int y = blockIdx.y;
    if (y < 16)
        hgemm_body(g_encH, g_WencH, b_enc, g_encP, ENC_DIM, JOINT_DIM,
                   y * 128, blockIdx.x * 128, smemBuf);
    else
        hgemm_body(g_predH, g_WpredH, b_pred, g_predP, PRED_DIM, JOINT_DIM,
                   (y - 16) * 128, blockIdx.x * 128, smemBuf);
}

// Fallback big GEMM (cp.async path) -- only used if TMA setup fails
__global__ void __launch_bounds__(256, 2)
legacy_gemm(const float* __restrict__ bias, float* __restrict__ C) {
    extern __shared__ __half smemBuf[];
    hgemm_body(g_A, g_WjH, bias, C, JOINT_DIM, VOCAB,
               blockIdx.y * 128, blockIdx.x * 128, smemBuf);
}

// ---------------------------------------------------------------------------
// Kernel 3: joint = tanh(enc_p[b,t,:] + pred_p[b,u,:]) -> fp16 A matrix.
// Register-resident enc slice, no smem, no sync.
// ---------------------------------------------------------------------------
__global__ void __launch_bounds__(256) joint_tanh_kernel() {
    const int bt = blockIdx.x;          // 0..2047
    const int tid = threadIdx.x;
    const int b = bt >> 8;
    const int j8 = (tid & 63) * 8;      // fixed 8-col slice
    const int ug = tid >> 6;            // 0..3

    const float4* encRow = reinterpret_cast<const float4*>(
        g_encP + (size_t)bt * JOINT_DIM + j8);
    const float4 e0 = encRow[0];
    const float4 e1 = encRow[1];

    const float* predBase = g_predP + (size_t)(b * UDIM) * JOINT_DIM + j8;
    __half* outBase = g_A + (size_t)bt * UDIM * JOINT_DIM + j8;

#pragma unroll 4
    for (int i = 0; i < 16; i++) {
        int u = i * 4 + ug;
        const float4* pp = reinterpret_cast<const float4*>(
            predBase + (size_t)u * JOINT_DIM);
        float4 p0 = pp[0], p1 = pp[1];
        __half2 h0 = __floats2half2_rn(tanh_ap(e0.x + p0.x), tanh_ap(e0.y + p0.y));
        __half2 h1 = __floats2half2_rn(tanh_ap(e0.z + p0.z), tanh_ap(e0.w + p0.w));
        __half2 h2 = __floats2half2_rn(tanh_ap(e1.x + p1.x), tanh_ap(e1.y + p1.y));
        __half2 h3 = __floats2half2_rn(tanh_ap(e1.z + p1.z), tanh_ap(e1.w + p1.w));
        uint4 o;
        o.x = *reinterpret_cast<uint32_t*>(&h0);
        o.y = *reinterpret_cast<uint32_t*>(&h1);
        o.z = *reinterpret_cast<uint32_t*>(&h2);
        o.w = *reinterpret_cast<uint32_t*>(&h3);
        *reinterpret_cast<uint4*>(outBase + (size_t)u * JOINT_DIM) = o;
    }
}

// ---------------------------------------------------------------------------
// Kernel 4: TMA big GEMM (round-5 proven config: CTA 128x128, warp 64x32,
// KSTEP 64, 3-stage, 2 CTAs/SM) with dead-barrier elimination: the
// end-of-iteration __syncthreads only guards the TMA refill, so it is
// skipped for the last TSTAGES tiles (no successor refill). Warps flow
// directly from the final mma into the register-private epilogue.
// ---------------------------------------------------------------------------
#define TKSTEP 64
#define TSTAGES 3
#define T_ASTG 16384                      // 128 rows x 128B
#define T_STG  32768                      // A + B per stage
#define TSMEM  (1024 + TSTAGES * T_STG)   // 99328 B

__global__ void __launch_bounds__(256, 2)
tma_gemm(const __grid_constant__ CUtensorMap mapA,
         const __grid_constant__ CUtensorMap mapB,
         const float* __restrict__ bias, float* __restrict__ C) {
    extern __shared__ __align__(128) char smt[];
    const uint32_t sb = s2u(smt);
    const int tid = threadIdx.x;
    const int lane = tid & 31;
    const int warp = tid >> 5;
    const int wm = warp >> 2;   // 0..1
    const int wn = warp & 3;    // 0..3
    const int m0 = blockIdx.y * 128;
    const int n0 = blockIdx.x * 128;

    if (tid == 0) {
#pragma unroll
        for (int s = 0; s < TSTAGES; s++) mbar_init(sb + s * 8, 1);
    }
    __syncthreads();

    if (tid == 0) {
#pragma unroll
        for (int p = 0; p < TSTAGES; p++) {
            uint32_t st = sb + 1024 + p * T_STG;
            mbar_expect_tx(sb + p * 8, T_STG);
            tma2d(st,          &mapA, p * TKSTEP, m0, sb + p * 8);
            tma2d(st + T_ASTG, &mapB, p * TKSTEP, n0, sb + p * 8);
        }
    }

    float c[4][4][4];
#pragma unroll
    for (int m = 0; m < 4; m++)
#pragma unroll
        for (int n = 0; n < 4; n++)
#pragma unroll
            for (int r = 0; r < 4; r++) c[m][n][r] = 0.f;

    int phase[TSTAGES] = {0, 0, 0};
    const int kTiles = JOINT_DIM / TKSTEP; // 8

#pragma unroll 1
    for (int kt = 0; kt < kTiles; ++kt) {
        const int s = kt % TSTAGES;
        mbar_wait(sb + s * 8, (uint32_t)phase[s]);
        phase[s] ^= 1;

        const char* aT = smt + 1024 + s * T_STG;
        const char* bT = aT + T_ASTG;

#pragma unroll
        for (int kk = 0; kk < 4; ++kk) {
            uint32_t af[4][4];
            uint32_t bf[2][4];
#pragma unroll
            for (int m = 0; m < 4; m++) {
                int R = wm * 64 + m * 16 + (lane & 15);
                uint32_t off = (uint32_t)(R * 128 + kk * 32 + (lane >> 4) * 16);
                off ^= (uint32_t)((R & 7) << 4);
                uint32_t sa = s2u(aT + off);
                asm volatile("ldmatrix.sync.aligned.m8n8.x4.shared.b16 {%0,%1,%2,%3}, [%4];\n"
                             : "=r"(af[m][0]), "=r"(af[m][1]), "=r"(af[m][2]), "=r"(af[m][3])
                             : "r"(sa));
            }
#pragma unroll
            for (int j = 0; j < 2; j++) {
                int lg = lane >> 3, rr = lane & 7;
                int nrow = wn * 32 + j * 16 + (lg >> 1) * 8 + rr;
                uint32_t off = (uint32_t)(nrow * 128 + kk * 32 + (lg & 1) * 16);
                off ^= (uint32_t)((nrow & 7) << 4);
                uint32_t sa = s2u(bT + off);
                asm volatile("ldmatrix.sync.aligned.m8n8.x4.shared.b16 {%0,%1,%2,%3}, [%4];\n"
                             : "=r"(bf[j][0]), "=r"(bf[j][1]), "=r"(bf[j][2]), "=r"(bf[j][3])
                             : "r"(sa));
            }
#pragma unroll
            for (int m = 0; m < 4; m++) {
#pragma unroll
                for (int n = 0; n < 4; n++) {
                    uint32_t b0 = bf[n >> 1][(n & 1) * 2];
                    uint32_t b1 = bf[n >> 1][(n & 1) * 2 + 1];
                    asm volatile(
                        "mma.sync.aligned.m16n8k16.row.col.f32.f16.f16.f32 "
                        "{%0,%1,%2,%3}, {%4,%5,%6,%7}, {%8,%9}, {%0,%1,%2,%3};\n"
                        : "+f"(c[m][n][0]), "+f"(c[m][n][1]), "+f"(c[m][n][2]), "+f"(c[m][n][3])
                        : "r"(af[m][0]), "r"(af[m][1]), "r"(af[m][2]), "r"(af[m][3]),
                          "r"(b0), "r"(b1));
                }
            }
        }

        // Barrier only when stage s will be refilled (kt+3 < 8). The last
        // TSTAGES iterations skip it: nothing reuses their stages, and the
        // epilogue touches only registers.
        if (kt + TSTAGES < kTiles) {
            __syncthreads();  // all consumers done with stage s
            if (tid == 0) {
                uint32_t st = sb + 1024 + s * T_STG;
                mbar_expect_tx(sb + s * 8, T_STG);
                tma2d(st,          &mapA, (kt + TSTAGES) * TKSTEP, m0, sb + s * 8);
                tma2d(st + T_ASTG, &mapB, (kt + TSTAGES) * TKSTEP, n0, sb + s * 8);
            }
        }
    }

    // epilogue (register-private; no barrier needed)
    const int mb = m0 + wm * 64;
    const int nb = n0 + wn * 32;
    float2 bb[4];
#pragma unroll
    for (int n = 0; n < 4; n++) {
        int col = nb + n * 8 + (lane & 3) * 2;
        bb[n].x = bias[col];
        bb[n].y = bias[col + 1];
    }
#pragma unroll
    for (int m = 0; m < 4; m++) {
        int row = mb + m * 16 + (lane >> 2);
#pragma unroll
        for (int n = 0; n < 4; n++) {
            int col = nb + n * 8 + (lane & 3) * 2;
            float2 v0 = make_float2(c[m][n][0] + bb[n].x, c[m][n][1] + bb[n].y);
            float2 v1 = make_float2(c[m][n][2] + bb[n].x, c[m][n][3] + bb[n].y);
            __stcs(reinterpret_cast<float2*>(C + (size_t)row * VOCAB + col), v0);
            __stcs(reinterpret_cast<float2*>(C + (size_t)(row + 8) * VOCAB + col), v1);
        }
    }
}

// ---------------------------------------------------------------------------
// Launch
// ---------------------------------------------------------------------------
static void* sym_addr(const void* s) {
    void* p = nullptr;
    cudaGetSymbolAddress(&p, s);
    return p;
}

typedef CUresult (CUDAAPI* PFN_tmEncode)(
    CUtensorMap*, CUtensorMapDataType, cuuint32_t, void*,
    const cuuint64_t*, const cuuint64_t*, const cuuint32_t*, const cuuint32_t*,
    CUtensorMapInterleave, CUtensorMapSwizzle, CUtensorMapL2promotion,
    CUtensorMapFloatOOBfill);

extern "C" void kernel_launch(void* const* d_in, const int* in_sizes, int n_in,
                              void* d_out, int out_size) {
    const float* enc_out = (const float*)d_in[0];
    const float* pred_out = (const float*)d_in[1];
    const float* W_enc = (const float*)d_in[2];
    const float* b_enc = (const float*)d_in[3];
    const float* W_pred = (const float*)d_in[4];
    const float* b_pred = (const float*)d_in[5];
    const float* W_joint = (const float*)d_in[6];
    const float* b_joint = (const float*)d_in[7];
    float* out = (float*)d_out;

    cudaFuncSetAttribute(proj_kernel,
                         cudaFuncAttributeMaxDynamicSharedMemorySize, SMEM_BYTES_L);
    cudaFuncSetAttribute(legacy_gemm,
                         cudaFuncAttributeMaxDynamicSharedMemorySize, SMEM_BYTES_L);
    cudaFuncSetAttribute(tma_gemm,
                         cudaFuncAttributeMaxDynamicSharedMemorySize, TSMEM);

    __half* Amat = (__half*)sym_addr(g_A);
    __half* WjT = (__half*)sym_addr(g_WjT);

    // 1) fp16 conversions + W_joint transpose (one launch)
    convert_kernel<<<2560, 256>>>(enc_out, pred_out, W_enc, W_pred, W_joint);

    // 2) both projections (one launch)
    proj_kernel<<<dim3(JOINT_DIM / 128, 20), 256, SMEM_BYTES_L>>>(b_enc, b_pred);

    // 3) joint tanh -> fp16 A
    joint_tanh_kernel<<<BATCH * TDIM, 256>>>();

    // 4) big GEMM: TMA path if tensor-map encode is available, else fallback
    bool ok = false;
    CUtensorMap mapA, mapB;
    void* fn = nullptr;
    cudaDriverEntryPointQueryResult qr;
    if (cudaGetDriverEntryPoint("cuTensorMapEncodeTiled", &fn,
                                cudaEnableDefault, &qr) == cudaSuccess && fn) {
        PFN_tmEncode encode = (PFN_tmEncode)fn;
        cuuint64_t dimsA[2] = {JOINT_DIM, MROWS};
        cuuint64_t dimsB[2] = {JOINT_DIM, VOCAB};
        cuuint64_t strides[1] = {JOINT_DIM * 2};
        cuuint32_t box[2] = {TKSTEP, 128};
        cuuint32_t es[2] = {1, 1};
        CUresult r1 = encode(&mapA, CU_TENSOR_MAP_DATA_TYPE_FLOAT16, 2, Amat,
                             dimsA, strides, box, es,
                             CU_TENSOR_MAP_INTERLEAVE_NONE,
                             CU_TENSOR_MAP_SWIZZLE_128B,
                             CU_TENSOR_MAP_L2_PROMOTION_L2_128B,
                             CU_TENSOR_MAP_FLOAT_OOB_FILL_NONE);
        CUresult r2 = encode(&mapB, CU_TENSOR_MAP_DATA_TYPE_FLOAT16, 2, WjT,
                             dimsB, strides, box, es,
                             CU_TENSOR_MAP_INTERLEAVE_NONE,
                             CU_TENSOR_MAP_SWIZZLE_128B,
                             CU_TENSOR_MAP_L2_PROMOTION_L2_128B,
                             CU_TENSOR_MAP_FLOAT_OOB_FILL_NONE);
        ok = (r1 == CUDA_SUCCESS) && (r2 == CUDA_SUCCESS);
    }
    if (ok) {
        tma_gemm<<<dim3(VOCAB / 128, MROWS / 128), 256, TSMEM>>>(
            mapA, mapB, b_joint, out);
    } else {
        legacy_gemm<<<dim3(VOCAB / 128, MROWS / 128), 256, SMEM_BYTES_L>>>(
            b_joint, out);
    }
}